// round 10
// baseline (speedup 1.0000x reference)
#include <cuda_runtime.h>
#include <cstdint>

#define NROWS 1024
#define MROWS 1024
#define DIM   512

__device__ float g_hx[NROWS * DIM];
__device__ float g_hy[MROWS * DIM];
__device__ float g_Wt[2 * DIM * DIM];   // Wt[z][n][k] = W1[z*DIM + k][n]

typedef unsigned long long u64;

#define ADD2(d, a, b) \
    asm("add.rn.f32x2 %0, %1, %2;" : "=l"(d) : "l"(a), "l"(b))
#define FMA2(d, a, b, c) \
    asm("fma.rn.f32x2 %0, %1, %2, %3;" : "=l"(d) : "l"(a), "l"(b), "l"(c))

__device__ __forceinline__ u64 relu2(u64 s) {
    unsigned int lo, hi;
    asm("mov.b64 {%0,%1}, %2;" : "=r"(lo), "=r"(hi) : "l"(s));
    float f0 = fmaxf(__uint_as_float(lo), 0.0f);
    float f1 = fmaxf(__uint_as_float(hi), 0.0f);
    u64 r;
    asm("mov.b64 %0, {%1,%2};"
        : "=l"(r) : "r"(__float_as_uint(f0)), "r"(__float_as_uint(f1)));
    return r;
}

__device__ __forceinline__ float hsum2(u64 s) {
    unsigned int lo, hi;
    asm("mov.b64 {%0,%1}, %2;" : "=r"(lo), "=r"(hi) : "l"(s));
    return __uint_as_float(lo) + __uint_as_float(hi);
}

__device__ __forceinline__ void cpa16(uint32_t s, const void* g) {
    asm volatile("cp.async.cg.shared.global [%0], [%1], 16;" :: "r"(s), "l"(g));
}
__device__ __forceinline__ void cpa8(uint32_t s, const void* g) {
    asm volatile("cp.async.ca.shared.global [%0], [%1], 8;" :: "r"(s), "l"(g));
}
#define CP_COMMIT() asm volatile("cp.async.commit_group;" ::: "memory")
#define CP_WAIT(n)  asm volatile("cp.async.wait_group %0;" :: "n"(n) : "memory")

// -------------------------------------------------------------------------
// W transpose: g_Wt[z][n][k] = W1[z*DIM + k][n]
// -------------------------------------------------------------------------
__global__ void __launch_bounds__(256) transpose_w(const float* __restrict__ W1) {
    __shared__ float t[32][33];
    const int z  = blockIdx.z;
    const int k0 = blockIdx.x * 32;
    const int n0 = blockIdx.y * 32;
    const int c  = threadIdx.x & 31;
    const int r0 = threadIdx.x >> 5;
#pragma unroll
    for (int rr = 0; rr < 4; rr++) {
        int r = r0 + rr * 8;
        t[r][c] = W1[(z * DIM + k0 + r) * DIM + n0 + c];
    }
    __syncthreads();
#pragma unroll
    for (int rr = 0; rr < 4; rr++) {
        int r = r0 + rr * 8;
        g_Wt[z * DIM * DIM + (n0 + r) * DIM + k0 + c] = t[c][r];
    }
}

// -------------------------------------------------------------------------
// GEMM: C[m][n] = sum_k A[m][k]*Wt[n][k].
// 64(m) x 32(n) tile -> grid (16,16,2) = 512 blocks. 4x2 per thread,
// strided (i = tm+16*ti, j = tn+16*tj). cp.async double-buffered, BK=32.
// As stride 36 (broadcast a-loads), Bs stride 34 (conflict-free LDS.64).
// -------------------------------------------------------------------------
__global__ void __launch_bounds__(256, 3) gemm_dual(const float* __restrict__ x,
                                                    const float* __restrict__ y) {
    const int z = blockIdx.z;
    const float* __restrict__ A  = (z == 0) ? x : y;
    const float* __restrict__ Wt = g_Wt + z * DIM * DIM;
    float* __restrict__ C = (z == 0) ? g_hx : g_hy;

    __shared__ float As[2][64][36];
    __shared__ float Bs[2][32][34];

    const int tid = threadIdx.x;
    const int tn = tid & 15;
    const int tm = tid >> 4;
    const int m0 = blockIdx.y * 64;
    const int n0 = blockIdx.x * 32;

    // A loader: 64 rows x 8 16B-chunks (2 iters of 32 rows)
    const int ar = tid >> 3;
    const int ac = tid & 7;
    // B loader: 32 rows x 16 8B-chunks (2 iters of 16 rows)
    const int br = tid >> 4;
    const int bc = tid & 15;

    uint32_t sAs[2], sBs[2];
    sAs[0] = (uint32_t)__cvta_generic_to_shared(&As[0][0][0]);
    sAs[1] = (uint32_t)__cvta_generic_to_shared(&As[1][0][0]);
    sBs[0] = (uint32_t)__cvta_generic_to_shared(&Bs[0][0][0]);
    sBs[1] = (uint32_t)__cvta_generic_to_shared(&Bs[1][0][0]);

    u64 acc[4][2];
#pragma unroll
    for (int i = 0; i < 4; i++)
#pragma unroll
        for (int j = 0; j < 2; j++) acc[i][j] = 0ULL;

    auto issue = [&](int bf, int k0) {
#pragma unroll
        for (int it = 0; it < 2; it++)
            cpa16(sAs[bf] + ((ar + it * 32) * 36 + ac * 4) * 4,
                  &A[(m0 + ar + it * 32) * DIM + k0 + ac * 4]);
#pragma unroll
        for (int it = 0; it < 2; it++)
            cpa8(sBs[bf] + ((br + it * 16) * 34 + bc * 2) * 4,
                 &Wt[(n0 + br + it * 16) * DIM + k0 + bc * 2]);
    };

    issue(0, 0);
    CP_COMMIT();

    for (int k0i = 0; k0i < 16; k0i++) {
        const int buf = k0i & 1;
        if (k0i < 15) {
            issue(buf ^ 1, (k0i + 1) * 32);
            CP_COMMIT();
            CP_WAIT(1);
        } else {
            CP_WAIT(0);
        }
        __syncthreads();

#pragma unroll
        for (int kk = 0; kk < 32; kk += 2) {
            u64 a2[4], b2[2];
#pragma unroll
            for (int i = 0; i < 4; i++)
                a2[i] = *(const u64*)&As[buf][tm + 16 * i][kk];
#pragma unroll
            for (int j = 0; j < 2; j++)
                b2[j] = *(const u64*)&Bs[buf][tn + 16 * j][kk];
#pragma unroll
            for (int i = 0; i < 4; i++)
#pragma unroll
                for (int j = 0; j < 2; j++)
                    FMA2(acc[i][j], a2[i], b2[j], acc[i][j]);
        }
        __syncthreads();
    }

#pragma unroll
    for (int i = 0; i < 4; i++)
#pragma unroll
        for (int j = 0; j < 2; j++)
            C[(m0 + tm + 16 * i) * DIM + n0 + tn + 16 * j] = hsum2(acc[i][j]);
}

// -------------------------------------------------------------------------
// Pairwise: out[i][j] = sum_d relu(hx[i][d]+hy[j][d]) * w2[d].
// 64(i) x 32(j) tile -> grid (32,16) = 512 blocks, full d, direct write.
// 4x2 per thread strided; cp.async double-buffered 32-d chunks.
// -------------------------------------------------------------------------
__global__ void __launch_bounds__(256, 3) pairwise_kernel(const float* __restrict__ w2,
                                                          float* __restrict__ out) {
    __shared__ float xs[2][64][36];
    __shared__ float ys[2][32][36];
    __shared__ float w2s[DIM];

    const int tid = threadIdx.x;
    const int tx = tid & 15;
    const int ty = tid >> 4;
    const int i0 = blockIdx.y * 64;
    const int j0 = blockIdx.x * 32;

    // xs loader: 64 rows x 8 chunks (2 iters); ys loader: 32 rows x 8 chunks
    const int xr = tid >> 3;
    const int xc = tid & 7;

    uint32_t sxs[2], sys[2];
    sxs[0] = (uint32_t)__cvta_generic_to_shared(&xs[0][0][0]);
    sxs[1] = (uint32_t)__cvta_generic_to_shared(&xs[1][0][0]);
    sys[0] = (uint32_t)__cvta_generic_to_shared(&ys[0][0][0]);
    sys[1] = (uint32_t)__cvta_generic_to_shared(&ys[1][0][0]);

    u64 acc[4][2];
#pragma unroll
    for (int i = 0; i < 4; i++)
#pragma unroll
        for (int j = 0; j < 2; j++) acc[i][j] = 0ULL;

    if (tid < 128)
        *(float4*)&w2s[tid * 4] = *(const float4*)&w2[tid * 4];

    auto issue = [&](int bf, int dg) {
#pragma unroll
        for (int it = 0; it < 2; it++)
            cpa16(sxs[bf] + ((xr + it * 32) * 36 + xc * 4) * 4,
                  &g_hx[(i0 + xr + it * 32) * DIM + dg + xc * 4]);
        cpa16(sys[bf] + (xr * 36 + xc * 4) * 4,
              &g_hy[(j0 + xr) * DIM + dg + xc * 4]);
    };

    issue(0, 0);
    CP_COMMIT();

    for (int ch = 0; ch < 16; ch++) {
        const int buf = ch & 1;
        if (ch < 15) {
            issue(buf ^ 1, (ch + 1) * 32);
            CP_COMMIT();
            CP_WAIT(1);
        } else {
            CP_WAIT(0);
        }
        __syncthreads();

        const float* __restrict__ w2p = &w2s[ch * 32];
#pragma unroll
        for (int dd = 0; dd < 32; dd += 4) {
            u64 a[4][2], b[2][2];
#pragma unroll
            for (int ti = 0; ti < 4; ti++) {
                ulonglong2 av = *(const ulonglong2*)&xs[buf][ty + 16 * ti][dd];
                a[ti][0] = av.x;
                a[ti][1] = av.y;
            }
#pragma unroll
            for (int tj = 0; tj < 2; tj++) {
                ulonglong2 bv = *(const ulonglong2*)&ys[buf][tx + 16 * tj][dd];
                b[tj][0] = bv.x;
                b[tj][1] = bv.y;
            }
            ulonglong2 wv = *(const ulonglong2*)&w2p[dd];
            u64 w[2];
            w[0] = wv.x;
            w[1] = wv.y;
#pragma unroll
            for (int ti = 0; ti < 4; ti++)
#pragma unroll
                for (int tj = 0; tj < 2; tj++) {
#pragma unroll
                    for (int p = 0; p < 2; p++) {
                        u64 s;
                        ADD2(s, a[ti][p], b[tj][p]);
                        s = relu2(s);
                        FMA2(acc[ti][tj], s, w[p], acc[ti][tj]);
                    }
                }
        }
        __syncthreads();
    }

#pragma unroll
    for (int ti = 0; ti < 4; ti++)
#pragma unroll
        for (int tj = 0; tj < 2; tj++)
            out[(i0 + ty + 16 * ti) * MROWS + j0 + tx + 16 * tj] =
                hsum2(acc[ti][tj]);
}

extern "C" void kernel_launch(void* const* d_in, const int* in_sizes, int n_in,
                              void* d_out, int out_size) {
    const float* x  = (const float*)d_in[0];
    const float* y  = (const float*)d_in[1];
    const float* W1 = (const float*)d_in[2];
    const float* W2 = (const float*)d_in[3];
    float* out = (float*)d_out;

    dim3 tgrid(DIM / 32, DIM / 32, 2);
    transpose_w<<<tgrid, 256>>>(W1);

    dim3 ggrid(DIM / 32, NROWS / 64, 2);     // 512 blocks
    gemm_dual<<<ggrid, 256>>>(x, y);

    dim3 pgrid(MROWS / 32, NROWS / 64);      // 512 blocks
    pairwise_kernel<<<pgrid, 256>>>(W2, out);
}

// round 11
// speedup vs baseline: 1.0342x; 1.0342x over previous
#include <cuda_runtime.h>
#include <cstdint>

#define NROWS 1024
#define MROWS 1024
#define DIM   512
#define DHALF 256

__device__ float g_hx[NROWS * DIM];
__device__ float g_hy[MROWS * DIM];

typedef unsigned long long u64;

#define ADD2(d, a, b) \
    asm("add.rn.f32x2 %0, %1, %2;" : "=l"(d) : "l"(a), "l"(b))
#define FMA2(d, a, b, c) \
    asm("fma.rn.f32x2 %0, %1, %2, %3;" : "=l"(d) : "l"(a), "l"(b), "l"(c))

__device__ __forceinline__ u64 relu2(u64 s) {
    unsigned int lo, hi;
    asm("mov.b64 {%0,%1}, %2;" : "=r"(lo), "=r"(hi) : "l"(s));
    float f0 = fmaxf(__uint_as_float(lo), 0.0f);
    float f1 = fmaxf(__uint_as_float(hi), 0.0f);
    u64 r;
    asm("mov.b64 %0, {%1,%2};"
        : "=l"(r) : "r"(__float_as_uint(f0)), "r"(__float_as_uint(f1)));
    return r;
}

__device__ __forceinline__ float hsum2(u64 s) {
    unsigned int lo, hi;
    asm("mov.b64 {%0,%1}, %2;" : "=r"(lo), "=r"(hi) : "l"(s));
    return __uint_as_float(lo) + __uint_as_float(hi);
}

__device__ __forceinline__ void cpa8(uint32_t s, const void* g) {
    asm volatile("cp.async.ca.shared.global [%0], [%1], 8;" :: "r"(s), "l"(g));
}
#define CP_COMMIT() asm volatile("cp.async.commit_group;" ::: "memory")
#define CP_WAIT(n)  asm volatile("cp.async.wait_group %0;" :: "n"(n) : "memory")

// -------------------------------------------------------------------------
// GEMM (R4 exact — best measured at 40.2us) + zero-out prologue.
// C[m][n] = sum_k A[m][k]*W[k][n]. 64x64 tile, BK=32, 4x4/thread,
// As stride 36 (broadcast a-loads), Bs stride 34, reg-staged double buffer.
// -------------------------------------------------------------------------
__global__ void __launch_bounds__(256, 2) gemm_dual(const float* __restrict__ x,
                                                    const float* __restrict__ y,
                                                    const float* __restrict__ W1,
                                                    float* __restrict__ out) {
    const int z = blockIdx.z;
    const float* __restrict__ A = (z == 0) ? x : y;
    const float* __restrict__ W = W1 + z * DIM * DIM;
    float* __restrict__ C = (z == 0) ? g_hx : g_hy;

    __shared__ float As[2][64][36];
    __shared__ float Bs[2][64][34];

    const int tid = threadIdx.x;
    const int tn = tid & 15;
    const int tm = tid >> 4;
    const int m0 = blockIdx.y * 64;
    const int n0 = blockIdx.x * 64;

    const int ar = tid >> 3;
    const int ac = tid & 7;
    const int wk = tid >> 4;
    const int wc = tid & 15;

    u64 acc[4][4];
#pragma unroll
    for (int i = 0; i < 4; i++)
#pragma unroll
        for (int j = 0; j < 4; j++) acc[i][j] = 0ULL;

    float4 aS[2], wS[2];
#pragma unroll
    for (int it = 0; it < 2; it++) {
        aS[it] = *(const float4*)&A[(m0 + ar + it * 32) * DIM + ac * 4];
        wS[it] = *(const float4*)&W[(wk + it * 16) * DIM + n0 + wc * 4];
    }

    // zero the final output buffer (each of the 256 blocks covers 4096 floats);
    // overlaps the global load latency above.
    {
        const int bid = (blockIdx.z * gridDim.y + blockIdx.y) * gridDim.x + blockIdx.x;
        float4 z4 = make_float4(0.f, 0.f, 0.f, 0.f);
        float* op = out + bid * 4096 + tid * 16;
#pragma unroll
        for (int q = 0; q < 4; q++) *(float4*)&op[q * 4] = z4;
    }

#pragma unroll
    for (int it = 0; it < 2; it++) {
        *(float4*)&As[0][ar + it * 32][ac * 4] = aS[it];
        Bs[0][wc * 4 + 0][wk + it * 16] = wS[it].x;
        Bs[0][wc * 4 + 1][wk + it * 16] = wS[it].y;
        Bs[0][wc * 4 + 2][wk + it * 16] = wS[it].z;
        Bs[0][wc * 4 + 3][wk + it * 16] = wS[it].w;
    }
    __syncthreads();

    for (int k0i = 0; k0i < 16; k0i++) {
        const int buf = k0i & 1;
        if (k0i < 15) {
            const int kng = (k0i + 1) * 32;
#pragma unroll
            for (int it = 0; it < 2; it++) {
                aS[it] = *(const float4*)&A[(m0 + ar + it * 32) * DIM + kng + ac * 4];
                wS[it] = *(const float4*)&W[(kng + wk + it * 16) * DIM + n0 + wc * 4];
            }
        }

#pragma unroll
        for (int kk = 0; kk < 32; kk += 2) {
            u64 a2[4], b2[4];
#pragma unroll
            for (int i = 0; i < 4; i++)
                a2[i] = *(const u64*)&As[buf][tm * 4 + i][kk];
#pragma unroll
            for (int j = 0; j < 4; j++)
                b2[j] = *(const u64*)&Bs[buf][tn + 16 * j][kk];
#pragma unroll
            for (int i = 0; i < 4; i++)
#pragma unroll
                for (int j = 0; j < 4; j++)
                    FMA2(acc[i][j], a2[i], b2[j], acc[i][j]);
        }

        if (k0i < 15) {
            const int nb = buf ^ 1;
#pragma unroll
            for (int it = 0; it < 2; it++) {
                *(float4*)&As[nb][ar + it * 32][ac * 4] = aS[it];
                Bs[nb][wc * 4 + 0][wk + it * 16] = wS[it].x;
                Bs[nb][wc * 4 + 1][wk + it * 16] = wS[it].y;
                Bs[nb][wc * 4 + 2][wk + it * 16] = wS[it].z;
                Bs[nb][wc * 4 + 3][wk + it * 16] = wS[it].w;
            }
        }
        __syncthreads();
    }

#pragma unroll
    for (int i = 0; i < 4; i++)
#pragma unroll
        for (int j = 0; j < 4; j++)
            C[(m0 + tm * 4 + i) * DIM + n0 + tn + 16 * j] = hsum2(acc[i][j]);
}

// -------------------------------------------------------------------------
// Pairwise: out[i][j] += sum_{d in half z} relu(hx[i][d]+hy[j][d]) * w2[d]
// 64x64 tile, z-split d -> grid (16,16,2) = 512 blocks, 4 blocks/SM.
// Stride-34 rows (odd 8B-granule stride -> conflict-free strided LDS.64),
// cp.async 8B loaders, double-buffered 32-d chunks, REDG epilogue.
// -------------------------------------------------------------------------
__global__ void __launch_bounds__(256, 4) pairwise_kernel(const float* __restrict__ w2,
                                                          float* __restrict__ out) {
    __shared__ float xs[2][64][34];
    __shared__ float ys[2][64][34];
    __shared__ float w2s[DHALF];

    const int tid = threadIdx.x;
    const int tx = tid & 15;
    const int ty = tid >> 4;
    const int i0 = blockIdx.y * 64;
    const int j0 = blockIdx.x * 64;
    const int dbase = blockIdx.z * DHALF;

    // loader: 64 rows x 16 8B-chunks; each thread: row lr, chunks lc,lc+4,lc+8,lc+12
    const int lr = tid >> 2;
    const int lc = tid & 3;

    uint32_t sxs[2], sys[2];
    sxs[0] = (uint32_t)__cvta_generic_to_shared(&xs[0][0][0]);
    sxs[1] = (uint32_t)__cvta_generic_to_shared(&xs[1][0][0]);
    sys[0] = (uint32_t)__cvta_generic_to_shared(&ys[0][0][0]);
    sys[1] = (uint32_t)__cvta_generic_to_shared(&ys[1][0][0]);

    u64 acc[4][4];
#pragma unroll
    for (int i = 0; i < 4; i++)
#pragma unroll
        for (int j = 0; j < 4; j++) acc[i][j] = 0ULL;

    if (tid < 64)
        *(float4*)&w2s[tid * 4] = *(const float4*)&w2[dbase + tid * 4];

    auto issue = [&](int bf, int dg) {
#pragma unroll
        for (int it = 0; it < 4; it++) {
            const int ch = lc + it * 4;            // 8B chunk 0..15
            cpa8(sxs[bf] + (lr * 34 + ch * 2) * 4,
                 &g_hx[(i0 + lr) * DIM + dbase + dg + ch * 2]);
            cpa8(sys[bf] + (lr * 34 + ch * 2) * 4,
                 &g_hy[(j0 + lr) * DIM + dbase + dg + ch * 2]);
        }
    };

    issue(0, 0);
    CP_COMMIT();

    for (int chk = 0; chk < 8; chk++) {
        const int buf = chk & 1;
        if (chk < 7) {
            issue(buf ^ 1, (chk + 1) * 32);
            CP_COMMIT();
            CP_WAIT(1);
        } else {
            CP_WAIT(0);
        }
        __syncthreads();

        const float* __restrict__ w2p = &w2s[chk * 32];
#pragma unroll
        for (int dd = 0; dd < 32; dd += 2) {
            u64 a[4], b[4], w;
            w = *(const u64*)&w2p[dd];
#pragma unroll
            for (int ti = 0; ti < 4; ti++)
                a[ti] = *(const u64*)&xs[buf][ty + 16 * ti][dd];
#pragma unroll
            for (int tj = 0; tj < 4; tj++)
                b[tj] = *(const u64*)&ys[buf][tx + 16 * tj][dd];
#pragma unroll
            for (int ti = 0; ti < 4; ti++)
#pragma unroll
                for (int tj = 0; tj < 4; tj++) {
                    u64 s;
                    ADD2(s, a[ti], b[tj]);
                    s = relu2(s);
                    FMA2(acc[ti][tj], s, w, acc[ti][tj]);
                }
        }
        __syncthreads();
    }

#pragma unroll
    for (int ti = 0; ti < 4; ti++)
#pragma unroll
        for (int tj = 0; tj < 4; tj++)
            atomicAdd(&out[(i0 + ty + 16 * ti) * MROWS + j0 + tx + 16 * tj],
                      hsum2(acc[ti][tj]));
}

extern "C" void kernel_launch(void* const* d_in, const int* in_sizes, int n_in,
                              void* d_out, int out_size) {
    const float* x  = (const float*)d_in[0];
    const float* y  = (const float*)d_in[1];
    const float* W1 = (const float*)d_in[2];
    const float* W2 = (const float*)d_in[3];
    float* out = (float*)d_out;

    dim3 ggrid(DIM / 64, NROWS / 64, 2);     // 256 blocks (also zeroes out)
    gemm_dual<<<ggrid, 256>>>(x, y, W1, out);

    dim3 pgrid(MROWS / 64, NROWS / 64, 2);   // 512 blocks
    pairwise_kernel<<<pgrid, 256>>>(W2, out);
}

// round 13
// speedup vs baseline: 1.0595x; 1.0245x over previous
#include <cuda_runtime.h>
#include <cstdint>

#define NROWS 1024
#define MROWS 1024
#define DIM   512
#define DHALF 256

__device__ float g_hx[NROWS * DIM];
__device__ float g_hy[MROWS * DIM];
__device__ float g_Wt[2 * DIM * DIM];   // Wt[z][n][k] = W1[z*DIM + k][n]

typedef unsigned long long u64;

#define ADD2(d, a, b) \
    asm("add.rn.f32x2 %0, %1, %2;" : "=l"(d) : "l"(a), "l"(b))
#define FMA2(d, a, b, c) \
    asm("fma.rn.f32x2 %0, %1, %2, %3;" : "=l"(d) : "l"(a), "l"(b), "l"(c))

// packed relu: 2 scalar FMNMX (alu pipe; dual-issues against FMA2 on fma pipe)
__device__ __forceinline__ u64 relu2(u64 s) {
    unsigned int lo, hi;
    asm("mov.b64 {%0,%1}, %2;" : "=r"(lo), "=r"(hi) : "l"(s));
    float f0 = fmaxf(__uint_as_float(lo), 0.0f);
    float f1 = fmaxf(__uint_as_float(hi), 0.0f);
    u64 r;
    asm("mov.b64 %0, {%1,%2};"
        : "=l"(r) : "r"(__float_as_uint(f0)), "r"(__float_as_uint(f1)));
    return r;
}

__device__ __forceinline__ float hsum2(u64 s) {
    unsigned int lo, hi;
    asm("mov.b64 {%0,%1}, %2;" : "=r"(lo), "=r"(hi) : "l"(s));
    return __uint_as_float(lo) + __uint_as_float(hi);
}

__device__ __forceinline__ void cpa16(uint32_t s, const void* g) {
    asm volatile("cp.async.cg.shared.global [%0], [%1], 16;" :: "r"(s), "l"(g));
}
#define CP_COMMIT() asm volatile("cp.async.commit_group;" ::: "memory")
#define CP_WAIT(n)  asm volatile("cp.async.wait_group %0;" :: "n"(n) : "memory")

// -------------------------------------------------------------------------
// W transpose: g_Wt[z][n][k] = W1[z*DIM + k][n]
// -------------------------------------------------------------------------
__global__ void __launch_bounds__(256) transpose_w(const float* __restrict__ W1) {
    __shared__ float t[32][33];
    const int z  = blockIdx.z;
    const int k0 = blockIdx.x * 32;
    const int n0 = blockIdx.y * 32;
    const int c  = threadIdx.x & 31;
    const int r0 = threadIdx.x >> 5;
#pragma unroll
    for (int rr = 0; rr < 4; rr++) {
        int r = r0 + rr * 8;
        t[r][c] = W1[(z * DIM + k0 + r) * DIM + n0 + c];
    }
    __syncthreads();
#pragma unroll
    for (int rr = 0; rr < 4; rr++) {
        int r = r0 + rr * 8;
        g_Wt[z * DIM * DIM + (n0 + r) * DIM + k0 + c] = t[c][r];
    }
}

// -------------------------------------------------------------------------
// GEMM v4: C[m][n] = sum_k A[m][k]*Wt[n][k].  Both operands k-contiguous,
// cp.async 16B direct copies (no STS transpose, no conflicts), stride 36
// rows (16B-aligned, odd granule -> conflict-free strided LDS.128).
// kk-step 4 with LDS.128 on both a and b. 64x64 tile, 4x4/thread.
// Also zeroes `out` in its prologue (overlaps first tile load).
// -------------------------------------------------------------------------
__global__ void __launch_bounds__(256, 3) gemm_dual(const float* __restrict__ x,
                                                    const float* __restrict__ y,
                                                    float* __restrict__ out) {
    const int z = blockIdx.z;
    const float* __restrict__ A  = (z == 0) ? x : y;
    const float* __restrict__ Wt = g_Wt + z * DIM * DIM;
    float* __restrict__ C = (z == 0) ? g_hx : g_hy;

    __shared__ float As[2][64][36];
    __shared__ float Bs[2][64][36];

    const int tid = threadIdx.x;
    const int tn = tid & 15;
    const int tm = tid >> 4;
    const int m0 = blockIdx.y * 64;
    const int n0 = blockIdx.x * 64;

    const int lr = tid >> 3;       // row 0..31, +32
    const int lc = tid & 7;        // 16B chunk

    uint32_t sAs[2], sBs[2];
    sAs[0] = (uint32_t)__cvta_generic_to_shared(&As[0][0][0]);
    sAs[1] = (uint32_t)__cvta_generic_to_shared(&As[1][0][0]);
    sBs[0] = (uint32_t)__cvta_generic_to_shared(&Bs[0][0][0]);
    sBs[1] = (uint32_t)__cvta_generic_to_shared(&Bs[1][0][0]);

    u64 acc[4][4];
#pragma unroll
    for (int i = 0; i < 4; i++)
#pragma unroll
        for (int j = 0; j < 4; j++) acc[i][j] = 0ULL;

    auto issue = [&](int bf, int k0) {
#pragma unroll
        for (int it = 0; it < 2; it++) {
            cpa16(sAs[bf] + ((lr + it * 32) * 36 + lc * 4) * 4,
                  &A[(m0 + lr + it * 32) * DIM + k0 + lc * 4]);
            cpa16(sBs[bf] + ((lr + it * 32) * 36 + lc * 4) * 4,
                  &Wt[(n0 + lr + it * 32) * DIM + k0 + lc * 4]);
        }
    };

    issue(0, 0);
    CP_COMMIT();

    // zero the output buffer (256 blocks x 4096 floats = full 1M)
    {
        const int bid = (blockIdx.z * gridDim.y + blockIdx.y) * gridDim.x + blockIdx.x;
        float4 z4 = make_float4(0.f, 0.f, 0.f, 0.f);
        float* op = out + bid * 4096 + tid * 16;
#pragma unroll
        for (int q = 0; q < 4; q++) *(float4*)&op[q * 4] = z4;
    }

    for (int k0i = 0; k0i < 16; k0i++) {
        const int buf = k0i & 1;
        if (k0i < 15) {
            issue(buf ^ 1, (k0i + 1) * 32);
            CP_COMMIT();
            CP_WAIT(1);
        } else {
            CP_WAIT(0);
        }
        __syncthreads();

#pragma unroll
        for (int kk = 0; kk < 32; kk += 4) {
            ulonglong2 av[4], bv[4];
#pragma unroll
            for (int i = 0; i < 4; i++)
                av[i] = *(const ulonglong2*)&As[buf][tm * 4 + i][kk];
#pragma unroll
            for (int j = 0; j < 4; j++)
                bv[j] = *(const ulonglong2*)&Bs[buf][tn + 16 * j][kk];
#pragma unroll
            for (int i = 0; i < 4; i++)
#pragma unroll
                for (int j = 0; j < 4; j++) {
                    FMA2(acc[i][j], av[i].x, bv[j].x, acc[i][j]);
                    FMA2(acc[i][j], av[i].y, bv[j].y, acc[i][j]);
                }
        }
        __syncthreads();
    }

#pragma unroll
    for (int i = 0; i < 4; i++)
#pragma unroll
        for (int j = 0; j < 4; j++)
            C[(m0 + tm * 4 + i) * DIM + n0 + tn + 16 * j] = hsum2(acc[i][j]);
}

// -------------------------------------------------------------------------
// Pairwise: out[i][j] += sum_{d in half z} relu(hx[i][d]+hy[j][d]) * w2[d]
// 64x64 tile, z-split d -> 512 blocks. cp.async 16B, stride-36 rows
// (conflict-free strided LDS.128), dd-step 4, atomicAdd epilogue.
// -------------------------------------------------------------------------
__global__ void __launch_bounds__(256, 3) pairwise_kernel(const float* __restrict__ w2,
                                                          float* __restrict__ out) {
    __shared__ float xs[2][64][36];
    __shared__ float ys[2][64][36];
    __shared__ float w2s[DHALF];

    const int tid = threadIdx.x;
    const int tx = tid & 15;
    const int ty = tid >> 4;
    const int i0 = blockIdx.y * 64;
    const int j0 = blockIdx.x * 64;
    const int dbase = blockIdx.z * DHALF;

    const int lr = tid >> 3;
    const int lc = tid & 7;

    uint32_t sxs[2], sys[2];
    sxs[0] = (uint32_t)__cvta_generic_to_shared(&xs[0][0][0]);
    sxs[1] = (uint32_t)__cvta_generic_to_shared(&xs[1][0][0]);
    sys[0] = (uint32_t)__cvta_generic_to_shared(&ys[0][0][0]);
    sys[1] = (uint32_t)__cvta_generic_to_shared(&ys[1][0][0]);

    u64 acc[4][4];
#pragma unroll
    for (int i = 0; i < 4; i++)
#pragma unroll
        for (int j = 0; j < 4; j++) acc[i][j] = 0ULL;

    if (tid < 64)
        *(float4*)&w2s[tid * 4] = *(const float4*)&w2[dbase + tid * 4];

    auto issue = [&](int bf, int dg) {
#pragma unroll
        for (int it = 0; it < 2; it++) {
            cpa16(sxs[bf] + ((lr + it * 32) * 36 + lc * 4) * 4,
                  &g_hx[(i0 + lr + it * 32) * DIM + dbase + dg + lc * 4]);
            cpa16(sys[bf] + ((lr + it * 32) * 36 + lc * 4) * 4,
                  &g_hy[(j0 + lr + it * 32) * DIM + dbase + dg + lc * 4]);
        }
    };

    issue(0, 0);
    CP_COMMIT();

    for (int chk = 0; chk < 8; chk++) {
        const int buf = chk & 1;
        if (chk < 7) {
            issue(buf ^ 1, (chk + 1) * 32);
            CP_COMMIT();
            CP_WAIT(1);
        } else {
            CP_WAIT(0);
        }
        __syncthreads();

        const float* __restrict__ w2p = &w2s[chk * 32];
#pragma unroll
        for (int dd = 0; dd < 32; dd += 4) {
            ulonglong2 av[4], bv[4];
#pragma unroll
            for (int ti = 0; ti < 4; ti++)
                av[ti] = *(const ulonglong2*)&xs[buf][ty + 16 * ti][dd];
#pragma unroll
            for (int tj = 0; tj < 4; tj++)
                bv[tj] = *(const ulonglong2*)&ys[buf][tx + 16 * tj][dd];
            ulonglong2 wv = *(const ulonglong2*)&w2p[dd];
#pragma unroll
            for (int ti = 0; ti < 4; ti++)
#pragma unroll
                for (int tj = 0; tj < 4; tj++) {
                    u64 s0, s1;
                    ADD2(s0, av[ti].x, bv[tj].x);
                    s0 = relu2(s0);
                    FMA2(acc[ti][tj], s0, wv.x, acc[ti][tj]);
                    ADD2(s1, av[ti].y, bv[tj].y);
                    s1 = relu2(s1);
                    FMA2(acc[ti][tj], s1, wv.y, acc[ti][tj]);
                }
        }
        __syncthreads();
    }

#pragma unroll
    for (int ti = 0; ti < 4; ti++)
#pragma unroll
        for (int tj = 0; tj < 4; tj++)
            atomicAdd(&out[(i0 + ty + 16 * ti) * MROWS + j0 + tx + 16 * tj],
                      hsum2(acc[ti][tj]));
}

extern "C" void kernel_launch(void* const* d_in, const int* in_sizes, int n_in,
                              void* d_out, int out_size) {
    const float* x  = (const float*)d_in[0];
    const float* y  = (const float*)d_in[1];
    const float* W1 = (const float*)d_in[2];
    const float* W2 = (const float*)d_in[3];
    float* out = (float*)d_out;

    dim3 tgrid(DIM / 32, DIM / 32, 2);
    transpose_w<<<tgrid, 256>>>(W1);

    dim3 ggrid(DIM / 64, NROWS / 64, 2);     // 256 blocks (also zeroes out)
    gemm_dual<<<ggrid, 256>>>(x, y, out);

    dim3 pgrid(MROWS / 64, NROWS / 64, 2);   // 512 blocks
    pairwise_kernel<<<pgrid, 256>>>(W2, out);
}

// round 14
// speedup vs baseline: 1.2483x; 1.1781x over previous
#include <cuda_runtime.h>
#include <cstdint>

#define NROWS 1024
#define MROWS 1024
#define DIM   512
#define DHALF 256

__device__ float g_hx[NROWS * DIM];
__device__ float g_hy[MROWS * DIM];
__device__ float g_xr[NROWS * DIM];     // tf32-rounded x
__device__ float g_yr[MROWS * DIM];     // tf32-rounded y
__device__ float g_Wt[2 * DIM * DIM];   // Wt[z][n][k] = tf32(W1[z*DIM + k][n])

typedef unsigned long long u64;

#define ADD2(d, a, b) \
    asm("add.rn.f32x2 %0, %1, %2;" : "=l"(d) : "l"(a), "l"(b))
#define FMA2(d, a, b, c) \
    asm("fma.rn.f32x2 %0, %1, %2, %3;" : "=l"(d) : "l"(a), "l"(b), "l"(c))

__device__ __forceinline__ u64 relu2(u64 s) {
    unsigned int lo, hi;
    asm("mov.b64 {%0,%1}, %2;" : "=r"(lo), "=r"(hi) : "l"(s));
    float f0 = fmaxf(__uint_as_float(lo), 0.0f);
    float f1 = fmaxf(__uint_as_float(hi), 0.0f);
    u64 r;
    asm("mov.b64 %0, {%1,%2};"
        : "=l"(r) : "r"(__float_as_uint(f0)), "r"(__float_as_uint(f1)));
    return r;
}

__device__ __forceinline__ float hsum2(u64 s) {
    unsigned int lo, hi;
    asm("mov.b64 {%0,%1}, %2;" : "=r"(lo), "=r"(hi) : "l"(s));
    return __uint_as_float(lo) + __uint_as_float(hi);
}

__device__ __forceinline__ float to_tf32(float f) {
    uint32_t u;
    asm("cvt.rna.tf32.f32 %0, %1;" : "=r"(u) : "f"(f));
    return __uint_as_float(u);
}

__device__ __forceinline__ void cpa16(uint32_t s, const void* g) {
    asm volatile("cp.async.cg.shared.global [%0], [%1], 16;" :: "r"(s), "l"(g));
}
#define CP_COMMIT() asm volatile("cp.async.commit_group;" ::: "memory")
#define CP_WAIT(n)  asm volatile("cp.async.wait_group %0;" :: "n"(n) : "memory")

#define MMA_TF32(c, a, b) \
    asm("mma.sync.aligned.m16n8k8.row.col.f32.tf32.tf32.f32 " \
        "{%0,%1,%2,%3}, {%4,%5,%6,%7}, {%8,%9}, {%0,%1,%2,%3};" \
        : "+f"((c)[0]), "+f"((c)[1]), "+f"((c)[2]), "+f"((c)[3]) \
        : "r"((a)[0]), "r"((a)[1]), "r"((a)[2]), "r"((a)[3]), \
          "r"((b)[0]), "r"((b)[1]))

// -------------------------------------------------------------------------
// Pre-round x,y to tf32 (unbiased RN) and zero the output buffer.
// grid 512 x 256 threads.
// -------------------------------------------------------------------------
__global__ void __launch_bounds__(256) round_xy(const float* __restrict__ x,
                                                const float* __restrict__ y,
                                                float* __restrict__ out) {
    const int t = blockIdx.x * 256 + threadIdx.x;   // 0..131071
    {
        float4 v = *(const float4*)&x[t * 4];
        v.x = to_tf32(v.x); v.y = to_tf32(v.y);
        v.z = to_tf32(v.z); v.w = to_tf32(v.w);
        *(float4*)&g_xr[t * 4] = v;
        float4 u = *(const float4*)&y[t * 4];
        u.x = to_tf32(u.x); u.y = to_tf32(u.y);
        u.z = to_tf32(u.z); u.w = to_tf32(u.w);
        *(float4*)&g_yr[t * 4] = u;
    }
    float4 z4 = make_float4(0.f, 0.f, 0.f, 0.f);
    *(float4*)&out[t * 8] = z4;
    *(float4*)&out[t * 8 + 4] = z4;
}

// -------------------------------------------------------------------------
// W transpose + tf32 round: g_Wt[z][n][k] = tf32(W1[z*DIM + k][n])
// -------------------------------------------------------------------------
__global__ void __launch_bounds__(256) transpose_w(const float* __restrict__ W1) {
    __shared__ float t[32][33];
    const int z  = blockIdx.z;
    const int k0 = blockIdx.x * 32;
    const int n0 = blockIdx.y * 32;
    const int c  = threadIdx.x & 31;
    const int r0 = threadIdx.x >> 5;
#pragma unroll
    for (int rr = 0; rr < 4; rr++) {
        int r = r0 + rr * 8;
        t[r][c] = to_tf32(W1[(z * DIM + k0 + r) * DIM + n0 + c]);
    }
    __syncthreads();
#pragma unroll
    for (int rr = 0; rr < 4; rr++) {
        int r = r0 + rr * 8;
        g_Wt[z * DIM * DIM + (n0 + r) * DIM + k0 + c] = t[c][r];
    }
}

// -------------------------------------------------------------------------
// Tensor-core GEMM: C[m][n] = sum_k A[m][k]*Wt[n][k] via tf32 m16n8k8.
// 64x64 block tile, 128 threads = 4 warps x (32x32) warp tiles.
// As/Bs stride-36 rows, cp.async double-buffered k-chunks of 32.
// Fragment LDS.32 patterns are conflict-free ((4g+tig) mod 32 distinct).
// -------------------------------------------------------------------------
__global__ void __launch_bounds__(128, 4) gemm_tc(const float* __restrict__ dummy) {
    const int z = blockIdx.z;
    const float* __restrict__ A  = (z == 0) ? g_xr : g_yr;
    const float* __restrict__ Wt = g_Wt + z * DIM * DIM;
    float* __restrict__ C = (z == 0) ? g_hx : g_hy;
    (void)dummy;

    __shared__ float As[2][64][36];
    __shared__ float Bs[2][64][36];

    const int tid  = threadIdx.x;
    const int wid  = tid >> 5;
    const int lane = tid & 31;
    const int g    = lane >> 2;    // 0..7
    const int tig  = lane & 3;     // 0..3
    const int wm   = (wid & 1) * 32;
    const int wn   = (wid >> 1) * 32;
    const int m0 = blockIdx.y * 64;
    const int n0 = blockIdx.x * 64;

    // loader: 64 rows x 8 16B-chunks, 128 threads -> 4 chunks each
    const int lrow = tid >> 1;
    const int lcp  = (tid & 1) * 4;

    uint32_t sAs[2], sBs[2];
    sAs[0] = (uint32_t)__cvta_generic_to_shared(&As[0][0][0]);
    sAs[1] = (uint32_t)__cvta_generic_to_shared(&As[1][0][0]);
    sBs[0] = (uint32_t)__cvta_generic_to_shared(&Bs[0][0][0]);
    sBs[1] = (uint32_t)__cvta_generic_to_shared(&Bs[1][0][0]);

    float c[2][4][4];
#pragma unroll
    for (int mi = 0; mi < 2; mi++)
#pragma unroll
        for (int nj = 0; nj < 4; nj++)
#pragma unroll
            for (int q = 0; q < 4; q++) c[mi][nj][q] = 0.0f;

    auto issue = [&](int bf, int k0) {
#pragma unroll
        for (int q = 0; q < 4; q++) {
            const int ch = lcp + q;
            cpa16(sAs[bf] + (lrow * 36 + ch * 4) * 4,
                  &A[(m0 + lrow) * DIM + k0 + ch * 4]);
            cpa16(sBs[bf] + (lrow * 36 + ch * 4) * 4,
                  &Wt[(n0 + lrow) * DIM + k0 + ch * 4]);
        }
    };

    issue(0, 0);
    CP_COMMIT();

    for (int k0i = 0; k0i < 16; k0i++) {
        const int buf = k0i & 1;
        if (k0i < 15) {
            issue(buf ^ 1, (k0i + 1) * 32);
            CP_COMMIT();
            CP_WAIT(1);
        } else {
            CP_WAIT(0);
        }
        __syncthreads();

#pragma unroll
        for (int ks = 0; ks < 4; ks++) {
            const int kb = ks * 8;
            uint32_t a[2][4], b[4][2];
#pragma unroll
            for (int mi = 0; mi < 2; mi++) {
                const int r = wm + mi * 16 + g;
                a[mi][0] = __float_as_uint(As[buf][r][kb + tig]);
                a[mi][1] = __float_as_uint(As[buf][r + 8][kb + tig]);
                a[mi][2] = __float_as_uint(As[buf][r][kb + 4 + tig]);
                a[mi][3] = __float_as_uint(As[buf][r + 8][kb + 4 + tig]);
            }
#pragma unroll
            for (int nj = 0; nj < 4; nj++) {
                const int n = wn + nj * 8 + g;
                b[nj][0] = __float_as_uint(Bs[buf][n][kb + tig]);
                b[nj][1] = __float_as_uint(Bs[buf][n][kb + 4 + tig]);
            }
#pragma unroll
            for (int mi = 0; mi < 2; mi++)
#pragma unroll
                for (int nj = 0; nj < 4; nj++)
                    MMA_TF32(c[mi][nj], a[mi], b[nj]);
        }
        __syncthreads();
    }

#pragma unroll
    for (int mi = 0; mi < 2; mi++)
#pragma unroll
        for (int nj = 0; nj < 4; nj++) {
            const int r  = m0 + wm + mi * 16 + g;
            const int cc = n0 + wn + nj * 8 + 2 * tig;
            *(float2*)&C[r * DIM + cc] = make_float2(c[mi][nj][0], c[mi][nj][1]);
            *(float2*)&C[(r + 8) * DIM + cc] = make_float2(c[mi][nj][2], c[mi][nj][3]);
        }
}

// -------------------------------------------------------------------------
// Pairwise (R13-exact): out[i][j] += sum_{d in half z} relu(hx+hy)*w2[d]
// 64x64 tile, z-split -> 512 blocks, cp.async, stride-36, atomicAdd.
// -------------------------------------------------------------------------
__global__ void __launch_bounds__(256, 3) pairwise_kernel(const float* __restrict__ w2,
                                                          float* __restrict__ out) {
    __shared__ float xs[2][64][36];
    __shared__ float ys[2][64][36];
    __shared__ float w2s[DHALF];

    const int tid = threadIdx.x;
    const int tx = tid & 15;
    const int ty = tid >> 4;
    const int i0 = blockIdx.y * 64;
    const int j0 = blockIdx.x * 64;
    const int dbase = blockIdx.z * DHALF;

    const int lr = tid >> 3;
    const int lc = tid & 7;

    uint32_t sxs[2], sys[2];
    sxs[0] = (uint32_t)__cvta_generic_to_shared(&xs[0][0][0]);
    sxs[1] = (uint32_t)__cvta_generic_to_shared(&xs[1][0][0]);
    sys[0] = (uint32_t)__cvta_generic_to_shared(&ys[0][0][0]);
    sys[1] = (uint32_t)__cvta_generic_to_shared(&ys[1][0][0]);

    u64 acc[4][4];
#pragma unroll
    for (int i = 0; i < 4; i++)
#pragma unroll
        for (int j = 0; j < 4; j++) acc[i][j] = 0ULL;

    if (tid < 64)
        *(float4*)&w2s[tid * 4] = *(const float4*)&w2[dbase + tid * 4];

    auto issue = [&](int bf, int dg) {
#pragma unroll
        for (int it = 0; it < 2; it++) {
            cpa16(sxs[bf] + ((lr + it * 32) * 36 + lc * 4) * 4,
                  &g_hx[(i0 + lr + it * 32) * DIM + dbase + dg + lc * 4]);
            cpa16(sys[bf] + ((lr + it * 32) * 36 + lc * 4) * 4,
                  &g_hy[(j0 + lr + it * 32) * DIM + dbase + dg + lc * 4]);
        }
    };

    issue(0, 0);
    CP_COMMIT();

    for (int chk = 0; chk < 8; chk++) {
        const int buf = chk & 1;
        if (chk < 7) {
            issue(buf ^ 1, (chk + 1) * 32);
            CP_COMMIT();
            CP_WAIT(1);
        } else {
            CP_WAIT(0);
        }
        __syncthreads();

        const float* __restrict__ w2p = &w2s[chk * 32];
#pragma unroll
        for (int dd = 0; dd < 32; dd += 4) {
            ulonglong2 av[4], bv[4];
#pragma unroll
            for (int ti = 0; ti < 4; ti++)
                av[ti] = *(const ulonglong2*)&xs[buf][ty + 16 * ti][dd];
#pragma unroll
            for (int tj = 0; tj < 4; tj++)
                bv[tj] = *(const ulonglong2*)&ys[buf][tx + 16 * tj][dd];
            ulonglong2 wv = *(const ulonglong2*)&w2p[dd];
#pragma unroll
            for (int ti = 0; ti < 4; ti++)
#pragma unroll
                for (int tj = 0; tj < 4; tj++) {
                    u64 s0, s1;
                    ADD2(s0, av[ti].x, bv[tj].x);
                    s0 = relu2(s0);
                    FMA2(acc[ti][tj], s0, wv.x, acc[ti][tj]);
                    ADD2(s1, av[ti].y, bv[tj].y);
                    s1 = relu2(s1);
                    FMA2(acc[ti][tj], s1, wv.y, acc[ti][tj]);
                }
        }
        __syncthreads();
    }

#pragma unroll
    for (int ti = 0; ti < 4; ti++)
#pragma unroll
        for (int tj = 0; tj < 4; tj++)
            atomicAdd(&out[(i0 + ty + 16 * ti) * MROWS + j0 + tx + 16 * tj],
                      hsum2(acc[ti][tj]));
}

extern "C" void kernel_launch(void* const* d_in, const int* in_sizes, int n_in,
                              void* d_out, int out_size) {
    const float* x  = (const float*)d_in[0];
    const float* y  = (const float*)d_in[1];
    const float* W1 = (const float*)d_in[2];
    const float* W2 = (const float*)d_in[3];
    float* out = (float*)d_out;

    round_xy<<<512, 256>>>(x, y, out);

    dim3 tgrid(DIM / 32, DIM / 32, 2);
    transpose_w<<<tgrid, 256>>>(W1);

    dim3 ggrid(DIM / 64, NROWS / 64, 2);     // 256 blocks, 128 thr
    gemm_tc<<<ggrid, 128>>>(x);

    dim3 pgrid(MROWS / 64, NROWS / 64, 2);   // 512 blocks
    pairwise_kernel<<<pgrid, 256>>>(W2, out);
}

// round 15
// speedup vs baseline: 1.2762x; 1.0224x over previous
#include <cuda_runtime.h>
#include <cstdint>

#define NROWS 1024
#define MROWS 1024
#define DIM   512
#define DHALF 256

__device__ float g_hx[NROWS * DIM];
__device__ float g_hy[MROWS * DIM];
__device__ float g_xr[NROWS * DIM];     // tf32-rounded x
__device__ float g_yr[MROWS * DIM];     // tf32-rounded y
__device__ float g_Wr[2 * DIM * DIM];   // tf32-rounded W1 (k-major, as given)

typedef unsigned long long u64;

#define ADD2(d, a, b) \
    asm("add.rn.f32x2 %0, %1, %2;" : "=l"(d) : "l"(a), "l"(b))
#define FMA2(d, a, b, c) \
    asm("fma.rn.f32x2 %0, %1, %2, %3;" : "=l"(d) : "l"(a), "l"(b), "l"(c))

__device__ __forceinline__ u64 relu2(u64 s) {
    unsigned int lo, hi;
    asm("mov.b64 {%0,%1}, %2;" : "=r"(lo), "=r"(hi) : "l"(s));
    float f0 = fmaxf(__uint_as_float(lo), 0.0f);
    float f1 = fmaxf(__uint_as_float(hi), 0.0f);
    u64 r;
    asm("mov.b64 %0, {%1,%2};"
        : "=l"(r) : "r"(__float_as_uint(f0)), "r"(__float_as_uint(f1)));
    return r;
}

__device__ __forceinline__ float hsum2(u64 s) {
    unsigned int lo, hi;
    asm("mov.b64 {%0,%1}, %2;" : "=r"(lo), "=r"(hi) : "l"(s));
    return __uint_as_float(lo) + __uint_as_float(hi);
}

__device__ __forceinline__ float to_tf32(float f) {
    uint32_t u;
    asm("cvt.rna.tf32.f32 %0, %1;" : "=r"(u) : "f"(f));
    return __uint_as_float(u);
}

// L1-allocating async copy (.ca): tiles of hx/hy are re-read by many blocks,
// .cg (L2-only) was costing ~200 cyc extra latency per reuse.
__device__ __forceinline__ void cpa16_ca(uint32_t s, const void* g) {
    asm volatile("cp.async.ca.shared.global [%0], [%1], 16;" :: "r"(s), "l"(g));
}
#define CP_COMMIT() asm volatile("cp.async.commit_group;" ::: "memory")
#define CP_WAIT(n)  asm volatile("cp.async.wait_group %0;" :: "n"(n) : "memory")

#define MMA_TF32(c, a, b) \
    asm("mma.sync.aligned.m16n8k8.row.col.f32.tf32.tf32.f32 " \
        "{%0,%1,%2,%3}, {%4,%5,%6,%7}, {%8,%9}, {%0,%1,%2,%3};" \
        : "+f"((c)[0]), "+f"((c)[1]), "+f"((c)[2]), "+f"((c)[3]) \
        : "r"((a)[0]), "r"((a)[1]), "r"((a)[2]), "r"((a)[3]), \
          "r"((b)[0]), "r"((b)[1]))

// -------------------------------------------------------------------------
// Pre-round x, y, W1 to tf32 (unbiased .rna) and zero the output buffer.
// -------------------------------------------------------------------------
__global__ void __launch_bounds__(256) round_all(const float* __restrict__ x,
                                                 const float* __restrict__ y,
                                                 const float* __restrict__ W1,
                                                 float* __restrict__ out) {
    const int t = blockIdx.x * 256 + threadIdx.x;   // 0..131071
    {
        float4 v = *(const float4*)&x[t * 4];
        v.x = to_tf32(v.x); v.y = to_tf32(v.y);
        v.z = to_tf32(v.z); v.w = to_tf32(v.w);
        *(float4*)&g_xr[t * 4] = v;
    }
    {
        float4 u = *(const float4*)&y[t * 4];
        u.x = to_tf32(u.x); u.y = to_tf32(u.y);
        u.z = to_tf32(u.z); u.w = to_tf32(u.w);
        *(float4*)&g_yr[t * 4] = u;
    }
    {
        float4 w = *(const float4*)&W1[t * 4];
        w.x = to_tf32(w.x); w.y = to_tf32(w.y);
        w.z = to_tf32(w.z); w.w = to_tf32(w.w);
        *(float4*)&g_Wr[t * 4] = w;
    }
    float4 z4 = make_float4(0.f, 0.f, 0.f, 0.f);
    *(float4*)&out[t * 8] = z4;
    *(float4*)&out[t * 8 + 4] = z4;
}

// -------------------------------------------------------------------------
// Tensor-core GEMM: C[m][n] = sum_k A[m][k]*W[k][n] via tf32 m16n8k8.
// B read directly from k-major W (no transpose kernel): Ws[k][n] stride 72
// -> b-frag banks (8*tig+g) mod 32 all distinct, conflict-free.
// 64x64 block tile, 128 threads = 4 warps x (32x32) warp tiles,
// cp.async.ca double-buffered k-chunks of 32.
// -------------------------------------------------------------------------
__global__ void __launch_bounds__(128, 4) gemm_tc() {
    const int z = blockIdx.z;
    const float* __restrict__ A = (z == 0) ? g_xr : g_yr;
    const float* __restrict__ W = g_Wr + z * DIM * DIM;
    float* __restrict__ C = (z == 0) ? g_hx : g_hy;

    __shared__ float As[2][64][36];
    __shared__ float Ws[2][32][72];

    const int tid  = threadIdx.x;
    const int wid  = tid >> 5;
    const int lane = tid & 31;
    const int g    = lane >> 2;    // 0..7
    const int tig  = lane & 3;     // 0..3
    const int wm   = (wid & 1) * 32;
    const int wn   = (wid >> 1) * 32;
    const int m0 = blockIdx.y * 64;
    const int n0 = blockIdx.x * 64;

    // A loader: 64 rows x 8 16B-chunks -> 4 per thread
    const int lrow = tid >> 1;
    const int lcp  = (tid & 1) * 4;
    // B loader: 32 k-rows x 16 16B-chunks -> 4 per thread
    const int brow = tid >> 2;
    const int bcp  = (tid & 3) * 4;

    uint32_t sAs[2], sWs[2];
    sAs[0] = (uint32_t)__cvta_generic_to_shared(&As[0][0][0]);
    sAs[1] = (uint32_t)__cvta_generic_to_shared(&As[1][0][0]);
    sWs[0] = (uint32_t)__cvta_generic_to_shared(&Ws[0][0][0]);
    sWs[1] = (uint32_t)__cvta_generic_to_shared(&Ws[1][0][0]);

    float c[2][4][4];
#pragma unroll
    for (int mi = 0; mi < 2; mi++)
#pragma unroll
        for (int nj = 0; nj < 4; nj++)
#pragma unroll
            for (int q = 0; q < 4; q++) c[mi][nj][q] = 0.0f;

    auto issue = [&](int bf, int k0) {
#pragma unroll
        for (int q = 0; q < 4; q++) {
            const int ch = lcp + q;
            cpa16_ca(sAs[bf] + (lrow * 36 + ch * 4) * 4,
                     &A[(m0 + lrow) * DIM + k0 + ch * 4]);
        }
#pragma unroll
        for (int q = 0; q < 4; q++) {
            const int ch = bcp + q;
            cpa16_ca(sWs[bf] + (brow * 72 + ch * 4) * 4,
                     &W[(k0 + brow) * DIM + n0 + ch * 4]);
        }
    };

    issue(0, 0);
    CP_COMMIT();

    for (int k0i = 0; k0i < 16; k0i++) {
        const int buf = k0i & 1;
        if (k0i < 15) {
            issue(buf ^ 1, (k0i + 1) * 32);
            CP_COMMIT();
            CP_WAIT(1);
        } else {
            CP_WAIT(0);
        }
        __syncthreads();

#pragma unroll
        for (int ks = 0; ks < 4; ks++) {
            const int kb = ks * 8;
            uint32_t a[2][4], b[4][2];
#pragma unroll
            for (int mi = 0; mi < 2; mi++) {
                const int r = wm + mi * 16 + g;
                a[mi][0] = __float_as_uint(As[buf][r][kb + tig]);
                a[mi][1] = __float_as_uint(As[buf][r + 8][kb + tig]);
                a[mi][2] = __float_as_uint(As[buf][r][kb + 4 + tig]);
                a[mi][3] = __float_as_uint(As[buf][r + 8][kb + 4 + tig]);
            }
#pragma unroll
            for (int nj = 0; nj < 4; nj++) {
                const int n = wn + nj * 8 + g;
                b[nj][0] = __float_as_uint(Ws[buf][kb + tig][n]);
                b[nj][1] = __float_as_uint(Ws[buf][kb + 4 + tig][n]);
            }
#pragma unroll
            for (int mi = 0; mi < 2; mi++)
#pragma unroll
                for (int nj = 0; nj < 4; nj++)
                    MMA_TF32(c[mi][nj], a[mi], b[nj]);
        }
        __syncthreads();
    }

#pragma unroll
    for (int mi = 0; mi < 2; mi++)
#pragma unroll
        for (int nj = 0; nj < 4; nj++) {
            const int r  = m0 + wm + mi * 16 + g;
            const int cc = n0 + wn + nj * 8 + 2 * tig;
            *(float2*)&C[r * DIM + cc] = make_float2(c[mi][nj][0], c[mi][nj][1]);
            *(float2*)&C[(r + 8) * DIM + cc] = make_float2(c[mi][nj][2], c[mi][nj][3]);
        }
}

// -------------------------------------------------------------------------
// Pairwise: out[i][j] += sum_{d in half z} relu(hx[i][d]+hy[j][d]) * w2[d]
// 64x64 tile, z-split -> 512 blocks. cp.async.ca (L1-cached!) 16B,
// stride-36 rows (conflict-free strided LDS.128), dd-step 4, atomicAdd.
// -------------------------------------------------------------------------
__global__ void __launch_bounds__(256, 3) pairwise_kernel(const float* __restrict__ w2,
                                                          float* __restrict__ out) {
    __shared__ float xs[2][64][36];
    __shared__ float ys[2][64][36];
    __shared__ float w2s[DHALF];

    const int tid = threadIdx.x;
    const int tx = tid & 15;
    const int ty = tid >> 4;
    const int i0 = blockIdx.y * 64;
    const int j0 = blockIdx.x * 64;
    const int dbase = blockIdx.z * DHALF;

    const int lr = tid >> 3;
    const int lc = tid & 7;

    uint32_t sxs[2], sys[2];
    sxs[0] = (uint32_t)__cvta_generic_to_shared(&xs[0][0][0]);
    sxs[1] = (uint32_t)__cvta_generic_to_shared(&xs[1][0][0]);
    sys[0] = (uint32_t)__cvta_generic_to_shared(&ys[0][0][0]);
    sys[1] = (uint32_t)__cvta_generic_to_shared(&ys[1][0][0]);

    u64 acc[4][4];
#pragma unroll
    for (int i = 0; i < 4; i++)
#pragma unroll
        for (int j = 0; j < 4; j++) acc[i][j] = 0ULL;

    if (tid < 64)
        *(float4*)&w2s[tid * 4] = *(const float4*)&w2[dbase + tid * 4];

    auto issue = [&](int bf, int dg) {
#pragma unroll
        for (int it = 0; it < 2; it++) {
            cpa16_ca(sxs[bf] + ((lr + it * 32) * 36 + lc * 4) * 4,
                     &g_hx[(i0 + lr + it * 32) * DIM + dbase + dg + lc * 4]);
            cpa16_ca(sys[bf] + ((lr + it * 32) * 36 + lc * 4) * 4,
                     &g_hy[(j0 + lr + it * 32) * DIM + dbase + dg + lc * 4]);
        }
    };

    issue(0, 0);
    CP_COMMIT();

    for (int chk = 0; chk < 8; chk++) {
        const int buf = chk & 1;
        if (chk < 7) {
            issue(buf ^ 1, (chk + 1) * 32);
            CP_COMMIT();
            CP_WAIT(1);
        } else {
            CP_WAIT(0);
        }
        __syncthreads();

        const float* __restrict__ w2p = &w2s[chk * 32];
#pragma unroll
        for (int dd = 0; dd < 32; dd += 4) {
            ulonglong2 av[4], bv[4];
#pragma unroll
            for (int ti = 0; ti < 4; ti++)
                av[ti] = *(const ulonglong2*)&xs[buf][ty + 16 * ti][dd];
#pragma unroll
            for (int tj = 0; tj < 4; tj++)
                bv[tj] = *(const ulonglong2*)&ys[buf][tx + 16 * tj][dd];
            ulonglong2 wv = *(const ulonglong2*)&w2p[dd];
#pragma unroll
            for (int ti = 0; ti < 4; ti++)
#pragma unroll
                for (int tj = 0; tj < 4; tj++) {
                    u64 s0, s1;
                    ADD2(s0, av[ti].x, bv[tj].x);
                    s0 = relu2(s0);
                    FMA2(acc[ti][tj], s0, wv.x, acc[ti][tj]);
                    ADD2(s1, av[ti].y, bv[tj].y);
                    s1 = relu2(s1);
                    FMA2(acc[ti][tj], s1, wv.y, acc[ti][tj]);
                }
        }
        __syncthreads();
    }

#pragma unroll
    for (int ti = 0; ti < 4; ti++)
#pragma unroll
        for (int tj = 0; tj < 4; tj++)
            atomicAdd(&out[(i0 + ty + 16 * ti) * MROWS + j0 + tx + 16 * tj],
                      hsum2(acc[ti][tj]));
}

extern "C" void kernel_launch(void* const* d_in, const int* in_sizes, int n_in,
                              void* d_out, int out_size) {
    const float* x  = (const float*)d_in[0];
    const float* y  = (const float*)d_in[1];
    const float* W1 = (const float*)d_in[2];
    const float* W2 = (const float*)d_in[3];
    float* out = (float*)d_out;

    round_all<<<512, 256>>>(x, y, W1, out);

    dim3 ggrid(DIM / 64, NROWS / 64, 2);     // 256 blocks, 128 thr
    gemm_tc<<<ggrid, 128>>>();

    dim3 pgrid(MROWS / 64, NROWS / 64, 2);   // 512 blocks
    pairwise_kernel<<<pgrid, 256>>>(W2, out);
}